// round 5
// baseline (speedup 1.0000x reference)
#include <cuda_runtime.h>
#include <cuda_bf16.h>
#include <cstdint>

#define TDIM 2048
#define DDIM 64
#define BQ 128
#define BK 64
#define NTH 256
#define KTILES (TDIM / BK)

// smem byte offsets: all tiles are [rows][64] bf16, 128B/row, SW128-swizzled
#define QH_OFF 0
#define QL_OFF 16384
#define KH_OFF 32768
#define KL_OFF 40960
#define VH_OFF 49152
#define VL_OFF 57344
#define PH_OFF 65536
#define PL_OFF 81920
#define SMEM_BYTES 98304

__device__ unsigned int g_maskbits[(size_t)TDIM * TDIM / 32];  // 512 KB bit-packed mask

// ---------------- helpers ----------------
__device__ __forceinline__ uint32_t smem_u32(const void* p) {
    uint32_t a;
    asm("{ .reg .u64 t; cvta.to.shared.u64 t, %1; cvt.u32.u64 %0, t; }" : "=r"(a) : "l"(p));
    return a;
}
__device__ __forceinline__ uint32_t swz(uint32_t byte) {
    return byte ^ ((byte >> 3) & 0x70);
}
__device__ __forceinline__ void ldsm_x4(uint32_t (&r)[4], uint32_t addr) {
    asm volatile("ldmatrix.sync.aligned.m8n8.x4.shared.b16 {%0,%1,%2,%3}, [%4];"
                 : "=r"(r[0]), "=r"(r[1]), "=r"(r[2]), "=r"(r[3]) : "r"(addr));
}
__device__ __forceinline__ void ldsm_x4_t(uint32_t (&r)[4], uint32_t addr) {
    asm volatile("ldmatrix.sync.aligned.m8n8.x4.trans.shared.b16 {%0,%1,%2,%3}, [%4];"
                 : "=r"(r[0]), "=r"(r[1]), "=r"(r[2]), "=r"(r[3]) : "r"(addr));
}
__device__ __forceinline__ void mma16816(float (&c)[4], const uint32_t (&a)[4],
                                         uint32_t b0, uint32_t b1) {
    asm volatile(
        "mma.sync.aligned.m16n8k16.row.col.f32.bf16.bf16.f32 "
        "{%0,%1,%2,%3}, {%4,%5,%6,%7}, {%8,%9}, {%0,%1,%2,%3};"
        : "+f"(c[0]), "+f"(c[1]), "+f"(c[2]), "+f"(c[3])
        : "r"(a[0]), "r"(a[1]), "r"(a[2]), "r"(a[3]), "r"(b0), "r"(b1));
}
// split 2 fp32 into bf16 hi/lo pairs, store 4B each into swizzled hi/lo tiles
__device__ __forceinline__ void cvt_pair_store(char* smem, uint32_t hi_off, uint32_t lo_off,
                                               uint32_t byte, float x, float y) {
    __nv_bfloat16 hx = __float2bfloat16(x), hy = __float2bfloat16(y);
    __nv_bfloat16 lx = __float2bfloat16(x - __bfloat162float(hx));
    __nv_bfloat16 ly = __float2bfloat16(y - __bfloat162float(hy));
    uint32_t hw = ((uint32_t)__bfloat16_as_ushort(hy) << 16) | __bfloat16_as_ushort(hx);
    uint32_t lw = ((uint32_t)__bfloat16_as_ushort(ly) << 16) | __bfloat16_as_ushort(lx);
    uint32_t sw = swz(byte);
    *(uint32_t*)(smem + hi_off + sw) = hw;
    *(uint32_t*)(smem + lo_off + sw) = lw;
}

// ---------------- mask bit-pack prepass ----------------
__global__ void pack_mask(const int* __restrict__ m) {
    int w = blockIdx.x * blockDim.x + threadIdx.x;
    if (w >= (TDIM * TDIM) / 32) return;
    const int4* p = (const int4*)(m + (size_t)w * 32);
    unsigned int bits = 0;
    #pragma unroll
    for (int i = 0; i < 8; ++i) {
        int4 v = p[i];
        bits |= (unsigned)(v.x != 0) << (i * 4);
        bits |= (unsigned)(v.y != 0) << (i * 4 + 1);
        bits |= (unsigned)(v.z != 0) << (i * 4 + 2);
        bits |= (unsigned)(v.w != 0) << (i * 4 + 3);
    }
    g_maskbits[w] = bits;
}

// ---------------- main attention kernel (warp-level HMMA, term-major ILP) ----
__global__ __launch_bounds__(NTH, 1)
void fa_mma(const float* __restrict__ gq, const float* __restrict__ gk,
            const float* __restrict__ gv, float* __restrict__ go)
{
    extern __shared__ char smem[];
    const uint32_t sb = smem_u32(smem);
    const int tid = threadIdx.x;
    const int lane = tid & 31, wid = tid >> 5;
    const int bh = blockIdx.y;
    const int q0 = blockIdx.x * BQ;
    const int m0 = wid * 16;          // warp's 16-row band of the Q tile

    const float* qb = gq + (size_t)bh * TDIM * DDIM;
    const float* kb = gk + (size_t)bh * TDIM * DDIM;
    const float* vb = gv + (size_t)bh * TDIM * DDIM;
    float*       ob = go + (size_t)bh * TDIM * DDIM;

    // ---- convert Q tile once (scaled by D^-0.5), bf16 hi/lo ----
    {
        const float4* q4 = (const float4*)(qb + (size_t)q0 * DDIM);
        #pragma unroll
        for (int it = 0; it < (BQ * DDIM / 4) / NTH; ++it) {
            int idx = tid + it * NTH;
            int row = idx >> 4, c4 = idx & 15;
            float4 v = q4[idx];
            v.x *= 0.125f; v.y *= 0.125f; v.z *= 0.125f; v.w *= 0.125f;
            uint32_t byte = row * 128 + c4 * 8;
            cvt_pair_store(smem, QH_OFF, QL_OFF, byte,     v.x, v.y);
            cvt_pair_store(smem, QH_OFF, QL_OFF, byte + 4, v.z, v.w);
        }
    }
    __syncthreads();

    // lane-invariant fragment address pieces
    const uint32_t arow  = m0 + ((lane >> 3) & 1) * 8 + (lane & 7);    // A-frag row
    const uint32_t acol0 = (lane >> 4) * 16;                            // A-frag col byte base
    const uint32_t brow  = ((lane >> 4) & 1) * 8 + (lane & 7);         // B-frag (S) row base
    const uint32_t bcol0 = ((lane >> 3) & 1) * 16;                     // B-frag (S) col byte base
    const uint32_t trow0 = ((lane >> 3) & 1) * 8 + (lane & 7);         // B-frag (PV, trans) row base
    const uint32_t tcol0 = ((lane >> 4) & 1) * 16;                     // B-frag (PV) col byte base

    // ---- preload Q fragments (reused across all 32 K-tiles) ----
    uint32_t aQh[4][4], aQl[4][4];
    #pragma unroll
    for (int ks = 0; ks < 4; ++ks) {
        uint32_t sw = swz(arow * 128 + ks * 32 + acol0);
        ldsm_x4(aQh[ks], sb + QH_OFF + sw);
        ldsm_x4(aQl[ks], sb + QL_OFF + sw);
    }

    float oreg[8][4];
    #pragma unroll
    for (int i = 0; i < 8; ++i)
        #pragma unroll
        for (int j = 0; j < 4; ++j) oreg[i][j] = 0.f;
    float lsum0 = 0.f, lsum1 = 0.f;

    const int g  = lane >> 2;         // row-in-band (fragment group)
    const int tq = lane & 3;          // col quad
    const int r0loc = m0 + g;         // local row (second row = +8)

    for (int kt = 0; kt < KTILES; ++kt) {
        const int k0 = kt * BK;
        __syncthreads();   // prior tile's ldmatrix consumers done before overwrite

        // ---- convert K and V tiles (64x64 each), bf16 hi/lo ----
        {
            const float4* k4 = (const float4*)(kb + (size_t)k0 * DDIM);
            const float4* v4 = (const float4*)(vb + (size_t)k0 * DDIM);
            #pragma unroll
            for (int it = 0; it < (BK * DDIM / 4) / NTH; ++it) {
                int idx = tid + it * NTH;
                int row = idx >> 4, c4 = idx & 15;
                uint32_t byte = row * 128 + c4 * 8;
                float4 kv = k4[idx];
                cvt_pair_store(smem, KH_OFF, KL_OFF, byte,     kv.x, kv.y);
                cvt_pair_store(smem, KH_OFF, KL_OFF, byte + 4, kv.z, kv.w);
                float4 vv = v4[idx];
                cvt_pair_store(smem, VH_OFF, VL_OFF, byte,     vv.x, vv.y);
                cvt_pair_store(smem, VH_OFF, VL_OFF, byte + 4, vv.z, vv.w);
            }
        }
        __syncthreads();

        // ---- S = Q K^T  (3-term bf16 emulation), term-major for 8-deep ILP ----
        float s[8][4];
        #pragma unroll
        for (int i = 0; i < 8; ++i)
            #pragma unroll
            for (int j = 0; j < 4; ++j) s[i][j] = 0.f;

        #pragma unroll
        for (int ks = 0; ks < 4; ++ks) {
            uint32_t bH[4][4], bL[4][4];
            #pragma unroll
            for (int np = 0; np < 4; ++np) {
                uint32_t sw = swz((np * 16 + brow) * 128 + ks * 32 + bcol0);
                ldsm_x4(bH[np], sb + KH_OFF + sw);
                ldsm_x4(bL[np], sb + KL_OFF + sw);
            }
            // term 1: Qhi*Khi — 8 independent accumulator chains
            #pragma unroll
            for (int np = 0; np < 4; ++np) {
                mma16816(s[2 * np],     aQh[ks], bH[np][0], bH[np][1]);
                mma16816(s[2 * np + 1], aQh[ks], bH[np][2], bH[np][3]);
            }
            // term 2: Qhi*Klo
            #pragma unroll
            for (int np = 0; np < 4; ++np) {
                mma16816(s[2 * np],     aQh[ks], bL[np][0], bL[np][1]);
                mma16816(s[2 * np + 1], aQh[ks], bL[np][2], bL[np][3]);
            }
            // term 3: Qlo*Khi
            #pragma unroll
            for (int np = 0; np < 4; ++np) {
                mma16816(s[2 * np],     aQl[ks], bH[np][0], bH[np][1]);
                mma16816(s[2 * np + 1], aQl[ks], bH[np][2], bH[np][3]);
            }
        }

        // ---- mask + exp + write P (warp-private rows; no barrier needed) ----
        {
            const unsigned long long* mp0 =
                (const unsigned long long*)(g_maskbits + (size_t)(q0 + r0loc) * (TDIM / 32) + kt * 2);
            const unsigned long long* mp1 =
                (const unsigned long long*)(g_maskbits + (size_t)(q0 + r0loc + 8) * (TDIM / 32) + kt * 2);
            unsigned long long mw0 = *mp0, mw1 = *mp1;
            #pragma unroll
            for (int ng = 0; ng < 8; ++ng) {
                int c = ng * 8 + tq * 2;
                float p0 = ((mw0 >> c) & 1ULL)       ? 0.f : __expf(s[ng][0]);
                float p1 = ((mw0 >> (c + 1)) & 1ULL) ? 0.f : __expf(s[ng][1]);
                float p2 = ((mw1 >> c) & 1ULL)       ? 0.f : __expf(s[ng][2]);
                float p3 = ((mw1 >> (c + 1)) & 1ULL) ? 0.f : __expf(s[ng][3]);
                lsum0 += p0 + p1;
                lsum1 += p2 + p3;
                cvt_pair_store(smem, PH_OFF, PL_OFF, (uint32_t)(r0loc * 128 + c * 2), p0, p1);
                cvt_pair_store(smem, PH_OFF, PL_OFF, (uint32_t)((r0loc + 8) * 128 + c * 2), p2, p3);
            }
        }

        // ---- O += P V  (3-term), term-major for 8-deep ILP ----
        #pragma unroll
        for (int ks = 0; ks < 4; ++ks) {
            uint32_t swA = swz(arow * 128 + ks * 32 + acol0);
            uint32_t aPh[4], aPl[4];
            ldsm_x4(aPh, sb + PH_OFF + swA);
            ldsm_x4(aPl, sb + PL_OFF + swA);
            uint32_t bH[4][4], bL[4][4];
            #pragma unroll
            for (int np = 0; np < 4; ++np) {
                uint32_t swB = swz((ks * 16 + trow0) * 128 + np * 32 + tcol0);
                ldsm_x4_t(bH[np], sb + VH_OFF + swB);
                ldsm_x4_t(bL[np], sb + VL_OFF + swB);
            }
            // term 1: Phi*Vhi
            #pragma unroll
            for (int np = 0; np < 4; ++np) {
                mma16816(oreg[2 * np],     aPh, bH[np][0], bH[np][1]);
                mma16816(oreg[2 * np + 1], aPh, bH[np][2], bH[np][3]);
            }
            // term 2: Phi*Vlo
            #pragma unroll
            for (int np = 0; np < 4; ++np) {
                mma16816(oreg[2 * np],     aPh, bL[np][0], bL[np][1]);
                mma16816(oreg[2 * np + 1], aPh, bL[np][2], bL[np][3]);
            }
            // term 3: Plo*Vhi
            #pragma unroll
            for (int np = 0; np < 4; ++np) {
                mma16816(oreg[2 * np],     aPl, bH[np][0], bH[np][1]);
                mma16816(oreg[2 * np + 1], aPl, bH[np][2], bH[np][3]);
            }
        }
    }

    // ---- epilogue: reduce row sums across the col-quad, normalize, store ----
    #pragma unroll
    for (int off = 1; off <= 2; off <<= 1) {
        lsum0 += __shfl_xor_sync(0xffffffffu, lsum0, off);
        lsum1 += __shfl_xor_sync(0xffffffffu, lsum1, off);
    }
    float inv0 = 1.f / lsum0;
    float inv1 = 1.f / lsum1;

    float* orow0 = ob + (size_t)(q0 + r0loc) * DDIM;
    float* orow1 = ob + (size_t)(q0 + r0loc + 8) * DDIM;
    #pragma unroll
    for (int ng = 0; ng < 8; ++ng) {
        int c = ng * 8 + tq * 2;
        float2 w0 = make_float2(oreg[ng][0] * inv0, oreg[ng][1] * inv0);
        float2 w1 = make_float2(oreg[ng][2] * inv1, oreg[ng][3] * inv1);
        *(float2*)(orow0 + c) = w0;
        *(float2*)(orow1 + c) = w1;
    }
}

extern "C" void kernel_launch(void* const* d_in, const int* in_sizes, int n_in,
                              void* d_out, int out_size) {
    const float* q = (const float*)d_in[0];
    const float* k = (const float*)d_in[1];
    const float* v = (const float*)d_in[2];
    const int* mask = (const int*)d_in[3];
    float* out = (float*)d_out;

    int bh = in_sizes[0] / (TDIM * DDIM);   // B*H = 32

    pack_mask<<<(TDIM * TDIM / 32 + 255) / 256, 256>>>(mask);

    cudaFuncSetAttribute(fa_mma, cudaFuncAttributeMaxDynamicSharedMemorySize, SMEM_BYTES);
    dim3 grid(TDIM / BQ, bh);
    fa_mma<<<grid, NTH, SMEM_BYTES>>>(q, k, v, out);
}

// round 6
// speedup vs baseline: 1.3232x; 1.3232x over previous
#include <cuda_runtime.h>
#include <cuda_bf16.h>
#include <cstdint>

#define TDIM 2048
#define DDIM 64
#define BH 32
#define BQ 128
#define BK 64
#define NTH 256
#define KTILES (TDIM / BK)

// smem layout (bytes): Q hi/lo [128][128B], P hi/lo [128][128B],
// K/V double-buffered stages: each stage {KH,KL,VH,VL} of 8KB
#define QH_OFF 0
#define QL_OFF 16384
#define PH_OFF 32768
#define PL_OFF 49152
#define KV_OFF 65536
#define KV_STAGE 32768
#define SMEM_BYTES (KV_OFF + 2 * KV_STAGE)   // 128 KB

#define NELEM ((size_t)BH * TDIM * DDIM)     // 4,194,304 per tensor

__device__ unsigned int g_maskbits[(size_t)TDIM * TDIM / 32];  // 512 KB
// bf16 hi/lo tensors, 16B-aligned for cp.async (uint4 = 8 bf16)
__device__ uint4 g_qh[NELEM / 8], g_ql[NELEM / 8];
__device__ uint4 g_kh[NELEM / 8], g_kl[NELEM / 8];
__device__ uint4 g_vh[NELEM / 8], g_vl[NELEM / 8];

// ---------------- helpers ----------------
__device__ __forceinline__ uint32_t smem_u32(const void* p) {
    uint32_t a;
    asm("{ .reg .u64 t; cvta.to.shared.u64 t, %1; cvt.u32.u64 %0, t; }" : "=r"(a) : "l"(p));
    return a;
}
__device__ __forceinline__ uint32_t swz(uint32_t byte) {
    return byte ^ ((byte >> 3) & 0x70);
}
__device__ __forceinline__ void cp16(uint32_t dst, const void* src) {
    asm volatile("cp.async.cg.shared.global [%0], [%1], 16;" :: "r"(dst), "l"(src));
}
#define CP_COMMIT() asm volatile("cp.async.commit_group;" ::: "memory")
#define CP_WAIT(n)  asm volatile("cp.async.wait_group %0;" :: "n"(n) : "memory")

__device__ __forceinline__ void ldsm_x4(uint32_t (&r)[4], uint32_t addr) {
    asm volatile("ldmatrix.sync.aligned.m8n8.x4.shared.b16 {%0,%1,%2,%3}, [%4];"
                 : "=r"(r[0]), "=r"(r[1]), "=r"(r[2]), "=r"(r[3]) : "r"(addr));
}
__device__ __forceinline__ void ldsm_x4_t(uint32_t (&r)[4], uint32_t addr) {
    asm volatile("ldmatrix.sync.aligned.m8n8.x4.trans.shared.b16 {%0,%1,%2,%3}, [%4];"
                 : "=r"(r[0]), "=r"(r[1]), "=r"(r[2]), "=r"(r[3]) : "r"(addr));
}
__device__ __forceinline__ void mma16816(float (&c)[4], const uint32_t (&a)[4],
                                         uint32_t b0, uint32_t b1) {
    asm volatile(
        "mma.sync.aligned.m16n8k16.row.col.f32.bf16.bf16.f32 "
        "{%0,%1,%2,%3}, {%4,%5,%6,%7}, {%8,%9}, {%0,%1,%2,%3};"
        : "+f"(c[0]), "+f"(c[1]), "+f"(c[2]), "+f"(c[3])
        : "r"(a[0]), "r"(a[1]), "r"(a[2]), "r"(a[3]), "r"(b0), "r"(b1));
}
__device__ __forceinline__ uint32_t pack_bf16x2(float x, float y) {
    __nv_bfloat16 hx = __float2bfloat16(x), hy = __float2bfloat16(y);
    return ((uint32_t)__bfloat16_as_ushort(hy) << 16) | __bfloat16_as_ushort(hx);
}
// split 2 fp32 into bf16 hi/lo pairs, store 4B each into swizzled hi/lo tiles
__device__ __forceinline__ void cvt_pair_store(char* smem, uint32_t hi_off, uint32_t lo_off,
                                               uint32_t byte, float x, float y) {
    __nv_bfloat16 hx = __float2bfloat16(x), hy = __float2bfloat16(y);
    float rx = x - __bfloat162float(hx), ry = y - __bfloat162float(hy);
    uint32_t sw = swz(byte);
    *(uint32_t*)(smem + hi_off + sw) =
        ((uint32_t)__bfloat16_as_ushort(hy) << 16) | __bfloat16_as_ushort(hx);
    *(uint32_t*)(smem + lo_off + sw) = pack_bf16x2(rx, ry);
}

// ---------------- prepass: mask bit-pack ----------------
__global__ void pack_mask(const int* __restrict__ m) {
    int w = blockIdx.x * blockDim.x + threadIdx.x;
    if (w >= (TDIM * TDIM) / 32) return;
    const int4* p = (const int4*)(m + (size_t)w * 32);
    unsigned int bits = 0;
    #pragma unroll
    for (int i = 0; i < 8; ++i) {
        int4 v = p[i];
        bits |= (unsigned)(v.x != 0) << (i * 4);
        bits |= (unsigned)(v.y != 0) << (i * 4 + 1);
        bits |= (unsigned)(v.z != 0) << (i * 4 + 2);
        bits |= (unsigned)(v.w != 0) << (i * 4 + 3);
    }
    g_maskbits[w] = bits;
}

// ---------------- prepass: fp32 -> bf16 hi/lo split (8 elems/thread) -------
__global__ void cvt_split(const float4* __restrict__ src, uint4* __restrict__ hi,
                          uint4* __restrict__ lo, float scale, int n16) {
    int i = blockIdx.x * blockDim.x + threadIdx.x;
    if (i >= n16) return;
    float4 a = src[2 * i], b = src[2 * i + 1];
    a.x *= scale; a.y *= scale; a.z *= scale; a.w *= scale;
    b.x *= scale; b.y *= scale; b.z *= scale; b.w *= scale;
    __nv_bfloat16 h[8] = {
        __float2bfloat16(a.x), __float2bfloat16(a.y), __float2bfloat16(a.z), __float2bfloat16(a.w),
        __float2bfloat16(b.x), __float2bfloat16(b.y), __float2bfloat16(b.z), __float2bfloat16(b.w)};
    uint4 hw, lw;
    hw.x = ((uint32_t)__bfloat16_as_ushort(h[1]) << 16) | __bfloat16_as_ushort(h[0]);
    hw.y = ((uint32_t)__bfloat16_as_ushort(h[3]) << 16) | __bfloat16_as_ushort(h[2]);
    hw.z = ((uint32_t)__bfloat16_as_ushort(h[5]) << 16) | __bfloat16_as_ushort(h[4]);
    hw.w = ((uint32_t)__bfloat16_as_ushort(h[7]) << 16) | __bfloat16_as_ushort(h[6]);
    lw.x = pack_bf16x2(a.x - __bfloat162float(h[0]), a.y - __bfloat162float(h[1]));
    lw.y = pack_bf16x2(a.z - __bfloat162float(h[2]), a.w - __bfloat162float(h[3]));
    lw.z = pack_bf16x2(b.x - __bfloat162float(h[4]), b.y - __bfloat162float(h[5]));
    lw.w = pack_bf16x2(b.z - __bfloat162float(h[6]), b.w - __bfloat162float(h[7]));
    hi[i] = hw;
    lo[i] = lw;
}

// ---------------- main attention kernel (HMMA + cp.async pipeline) --------
__global__ __launch_bounds__(NTH, 1)
void fa_mma(float* __restrict__ go)
{
    extern __shared__ char smem[];
    const uint32_t sb = smem_u32(smem);
    const int tid = threadIdx.x;
    const int lane = tid & 31, wid = tid >> 5;
    const int bh = blockIdx.y;
    const int q0 = blockIdx.x * BQ;
    const int m0 = wid * 16;          // warp's 16-row band of the Q tile

    const size_t row_bytes = 128;     // 64 bf16 per row
    const char* gqh = (const char*)g_qh + ((size_t)bh * TDIM + q0) * row_bytes;
    const char* gql = (const char*)g_ql + ((size_t)bh * TDIM + q0) * row_bytes;
    const char* gkh0 = (const char*)g_kh + (size_t)bh * TDIM * row_bytes;
    const char* gkl0 = (const char*)g_kl + (size_t)bh * TDIM * row_bytes;
    const char* gvh0 = (const char*)g_vh + (size_t)bh * TDIM * row_bytes;
    const char* gvl0 = (const char*)g_vl + (size_t)bh * TDIM * row_bytes;
    float* ob = go + (size_t)bh * TDIM * DDIM;

    // ---- prologue: async-load Q tile (hi/lo, 16KB each) ----
    #pragma unroll
    for (int j = 0; j < 4; ++j) {
        uint32_t byte = tid * 16 + j * 4096;
        uint32_t sw = swz(byte);
        cp16(sb + QH_OFF + sw, gqh + byte);
        cp16(sb + QL_OFF + sw, gql + byte);
    }
    CP_COMMIT();

    // ---- issue K/V tile 0 into stage 0 ----
    {
        const size_t toff = 0;
        #pragma unroll
        for (int j = 0; j < 2; ++j) {
            uint32_t byte = (tid + j * 256) * 16;
            uint32_t sw = swz(byte);
            uint32_t base = sb + KV_OFF;
            cp16(base + sw,          gkh0 + toff + byte);
            cp16(base + 8192 + sw,   gkl0 + toff + byte);
            cp16(base + 16384 + sw,  gvh0 + toff + byte);
            cp16(base + 24576 + sw,  gvl0 + toff + byte);
        }
    }
    CP_COMMIT();
    CP_WAIT(1);            // Q resident (tile-0 group may still be in flight)
    __syncthreads();

    // lane-invariant fragment address pieces
    const uint32_t arow  = m0 + ((lane >> 3) & 1) * 8 + (lane & 7);
    const uint32_t acol0 = (lane >> 4) * 16;
    const uint32_t brow  = ((lane >> 4) & 1) * 8 + (lane & 7);
    const uint32_t bcol0 = ((lane >> 3) & 1) * 16;
    const uint32_t trow0 = ((lane >> 3) & 1) * 8 + (lane & 7);
    const uint32_t tcol0 = ((lane >> 4) & 1) * 16;

    // ---- preload Q fragments (reused across all K-tiles) ----
    uint32_t aQh[4][4], aQl[4][4];
    #pragma unroll
    for (int ks = 0; ks < 4; ++ks) {
        uint32_t sw = swz(arow * 128 + ks * 32 + acol0);
        ldsm_x4(aQh[ks], sb + QH_OFF + sw);
        ldsm_x4(aQl[ks], sb + QL_OFF + sw);
    }

    float oreg[8][4];
    #pragma unroll
    for (int i = 0; i < 8; ++i)
        #pragma unroll
        for (int j = 0; j < 4; ++j) oreg[i][j] = 0.f;
    float lsum0 = 0.f, lsum1 = 0.f;

    const int g  = lane >> 2;
    const int tq = lane & 3;
    const int r0loc = m0 + g;

    for (int kt = 0; kt < KTILES; ++kt) {
        // ---- prefetch next tile into alternate stage ----
        if (kt + 1 < KTILES) {
            const size_t toff = (size_t)(kt + 1) * BK * row_bytes;
            uint32_t base = sb + KV_OFF + ((kt + 1) & 1) * KV_STAGE;
            #pragma unroll
            for (int j = 0; j < 2; ++j) {
                uint32_t byte = (tid + j * 256) * 16;
                uint32_t sw = swz(byte);
                cp16(base + sw,         gkh0 + toff + byte);
                cp16(base + 8192 + sw,  gkl0 + toff + byte);
                cp16(base + 16384 + sw, gvh0 + toff + byte);
                cp16(base + 24576 + sw, gvl0 + toff + byte);
            }
            CP_COMMIT();
            CP_WAIT(1);    // current tile's group complete
        } else {
            CP_WAIT(0);
        }

        // early mask fetch (independent LDG)
        unsigned long long mw0 =
            *(const unsigned long long*)(g_maskbits + (size_t)(q0 + r0loc) * (TDIM / 32) + kt * 2);
        unsigned long long mw1 =
            *(const unsigned long long*)(g_maskbits + (size_t)(q0 + r0loc + 8) * (TDIM / 32) + kt * 2);
        __syncthreads();   // tile visible to all warps

        const uint32_t kvb = sb + KV_OFF + (kt & 1) * KV_STAGE;
        const uint32_t khb = kvb, klb = kvb + 8192, vhb = kvb + 16384, vlb = kvb + 24576;

        // ---- S = Q K^T (3-term bf16 emulation) ----
        float s[8][4];
        #pragma unroll
        for (int i = 0; i < 8; ++i)
            #pragma unroll
            for (int j = 0; j < 4; ++j) s[i][j] = 0.f;

        #pragma unroll
        for (int ks = 0; ks < 4; ++ks) {
            uint32_t bHf[4][4], bLf[4][4];
            #pragma unroll
            for (int np = 0; np < 4; ++np) {
                uint32_t sw = swz((np * 16 + brow) * 128 + ks * 32 + bcol0);
                ldsm_x4(bHf[np], khb + sw);
                ldsm_x4(bLf[np], klb + sw);
            }
            #pragma unroll
            for (int np = 0; np < 4; ++np) {
                mma16816(s[2 * np],     aQh[ks], bHf[np][0], bHf[np][1]);
                mma16816(s[2 * np + 1], aQh[ks], bHf[np][2], bHf[np][3]);
            }
            #pragma unroll
            for (int np = 0; np < 4; ++np) {
                mma16816(s[2 * np],     aQh[ks], bLf[np][0], bLf[np][1]);
                mma16816(s[2 * np + 1], aQh[ks], bLf[np][2], bLf[np][3]);
            }
            #pragma unroll
            for (int np = 0; np < 4; ++np) {
                mma16816(s[2 * np],     aQl[ks], bHf[np][0], bHf[np][1]);
                mma16816(s[2 * np + 1], aQl[ks], bHf[np][2], bHf[np][3]);
            }
        }

        // ---- mask + exp + write P (warp-private rows) ----
        #pragma unroll
        for (int ng = 0; ng < 8; ++ng) {
            int c = ng * 8 + tq * 2;
            float p0 = ((mw0 >> c) & 1ULL)       ? 0.f : __expf(s[ng][0]);
            float p1 = ((mw0 >> (c + 1)) & 1ULL) ? 0.f : __expf(s[ng][1]);
            float p2 = ((mw1 >> c) & 1ULL)       ? 0.f : __expf(s[ng][2]);
            float p3 = ((mw1 >> (c + 1)) & 1ULL) ? 0.f : __expf(s[ng][3]);
            lsum0 += p0 + p1;
            lsum1 += p2 + p3;
            cvt_pair_store(smem, PH_OFF, PL_OFF, (uint32_t)(r0loc * 128 + c * 2), p0, p1);
            cvt_pair_store(smem, PH_OFF, PL_OFF, (uint32_t)((r0loc + 8) * 128 + c * 2), p2, p3);
        }

        // ---- O += P V (3-term), V via ldmatrix.trans ----
        #pragma unroll
        for (int ks = 0; ks < 4; ++ks) {
            uint32_t swA = swz(arow * 128 + ks * 32 + acol0);
            uint32_t aPh[4], aPl[4];
            ldsm_x4(aPh, sb + PH_OFF + swA);
            ldsm_x4(aPl, sb + PL_OFF + swA);
            uint32_t bHf[4][4], bLf[4][4];
            #pragma unroll
            for (int np = 0; np < 4; ++np) {
                uint32_t swB = swz((ks * 16 + trow0) * 128 + np * 32 + tcol0);
                ldsm_x4_t(bHf[np], vhb + swB);
                ldsm_x4_t(bLf[np], vlb + swB);
            }
            #pragma unroll
            for (int np = 0; np < 4; ++np) {
                mma16816(oreg[2 * np],     aPh, bHf[np][0], bHf[np][1]);
                mma16816(oreg[2 * np + 1], aPh, bHf[np][2], bHf[np][3]);
            }
            #pragma unroll
            for (int np = 0; np < 4; ++np) {
                mma16816(oreg[2 * np],     aPh, bLf[np][0], bLf[np][1]);
                mma16816(oreg[2 * np + 1], aPh, bLf[np][2], bLf[np][3]);
            }
            #pragma unroll
            for (int np = 0; np < 4; ++np) {
                mma16816(oreg[2 * np],     aPl, bHf[np][0], bHf[np][1]);
                mma16816(oreg[2 * np + 1], aPl, bHf[np][2], bHf[np][3]);
            }
        }
        __syncthreads();   // stage (kt+1)&1 safe to refill next iteration
    }

    // ---- epilogue ----
    #pragma unroll
    for (int off = 1; off <= 2; off <<= 1) {
        lsum0 += __shfl_xor_sync(0xffffffffu, lsum0, off);
        lsum1 += __shfl_xor_sync(0xffffffffu, lsum1, off);
    }
    float inv0 = 1.f / lsum0;
    float inv1 = 1.f / lsum1;

    float* orow0 = ob + (size_t)(q0 + r0loc) * DDIM;
    float* orow1 = ob + (size_t)(q0 + r0loc + 8) * DDIM;
    #pragma unroll
    for (int ng = 0; ng < 8; ++ng) {
        int c = ng * 8 + tq * 2;
        *(float2*)(orow0 + c) = make_float2(oreg[ng][0] * inv0, oreg[ng][1] * inv0);
        *(float2*)(orow1 + c) = make_float2(oreg[ng][2] * inv1, oreg[ng][3] * inv1);
    }
}

extern "C" void kernel_launch(void* const* d_in, const int* in_sizes, int n_in,
                              void* d_out, int out_size) {
    const float* q = (const float*)d_in[0];
    const float* k = (const float*)d_in[1];
    const float* v = (const float*)d_in[2];
    const int* mask = (const int*)d_in[3];
    float* out = (float*)d_out;

    uint4 *qh, *ql, *kh, *kl, *vh, *vl;
    cudaGetSymbolAddress((void**)&qh, g_qh);
    cudaGetSymbolAddress((void**)&ql, g_ql);
    cudaGetSymbolAddress((void**)&kh, g_kh);
    cudaGetSymbolAddress((void**)&kl, g_kl);
    cudaGetSymbolAddress((void**)&vh, g_vh);
    cudaGetSymbolAddress((void**)&vl, g_vl);

    pack_mask<<<(TDIM * TDIM / 32 + 255) / 256, 256>>>(mask);

    const int n16 = (int)(NELEM / 8);
    cvt_split<<<(n16 + 255) / 256, 256>>>((const float4*)q, qh, ql, 0.125f, n16);
    cvt_split<<<(n16 + 255) / 256, 256>>>((const float4*)k, kh, kl, 1.0f, n16);
    cvt_split<<<(n16 + 255) / 256, 256>>>((const float4*)v, vh, vl, 1.0f, n16);

    cudaFuncSetAttribute(fa_mma, cudaFuncAttributeMaxDynamicSharedMemorySize, SMEM_BYTES);
    dim3 grid(TDIM / BQ, BH);
    fa_mma<<<grid, NTH, SMEM_BYTES>>>(out);
}